// round 14
// baseline (speedup 1.0000x reference)
#include <cuda_runtime.h>
#include <cstdint>
#include <math.h>

#define EPS 1e-5f
typedef unsigned long long ull;

// ---------------- f32x2 packed helpers ----------------
__device__ __forceinline__ ull pk2(float lo, float hi) {
    ull r; asm("mov.b64 %0,{%1,%2};" : "=l"(r) : "f"(lo), "f"(hi)); return r;
}
__device__ __forceinline__ void unpk2(float& lo, float& hi, ull v) {
    asm("mov.b64 {%0,%1},%2;" : "=f"(lo), "=f"(hi) : "l"(v));
}
__device__ __forceinline__ ull fma2(ull a, ull b, ull c) {
    ull d; asm("fma.rn.f32x2 %0,%1,%2,%3;" : "=l"(d) : "l"(a), "l"(b), "l"(c)); return d;
}
#define CP_ASYNC16(dst, src) \
    asm volatile("cp.async.ca.shared.global [%0], [%1], 16;" :: "r"(dst), "l"(src))
#define CP_COMMIT() asm volatile("cp.async.commit_group;" ::: "memory")
#define CP_WAIT2() asm volatile("cp.async.wait_group 2;" ::: "memory")
#define CP_WAIT1() asm volatile("cp.async.wait_group 1;" ::: "memory")
#define CP_WAIT0() asm volatile("cp.async.wait_group 0;" ::: "memory")

// ---------------- scratch (device globals; no allocations) ----------------
__device__ float g_xn[512 * 768];
__device__ float g_qkv[512 * 2304];
__device__ float g_qh[12 * 512 * 64];    // [h][i][d], q * scale
__device__ float g_kT[12 * 64 * 512];    // [h][d][j]
__device__ float g_vh[12 * 512 * 64];    // [h][j][d]
__device__ __align__(16) float g_gW[768 * 12];  // pair_g[c] * Wbias[c][h]
__device__ float g_GW[12];
__device__ float g_BW[12];
__device__ float g_bias[12 * 512 * 512]; // [h][i][j]; j>i stays 0 (.bss)
__device__ float g_sim[12 * 512 * 512];  // [h][i][j], reused as attn
__device__ float g_attout[512 * 768];    // [i][h*64+d]

// ---------------- precompute gW, GW, BW ----------------
__global__ void precompute_gw(const float* __restrict__ pg,
                              const float* __restrict__ pb,
                              const float* __restrict__ Wb) {
    int t = threadIdx.x; // 384
    for (int idx = t; idx < 768 * 12; idx += 384)
        g_gW[idx] = pg[idx / 12] * Wb[idx];
    int w = t >> 5, l = t & 31;
    if (w < 12) {
        float gw = 0.f, bw = 0.f;
        for (int c = l; c < 768; c += 32) {
            float wv = Wb[c * 12 + w];
            gw = fmaf(pg[c], wv, gw);
            bw = fmaf(pb[c], wv, bw);
        }
#pragma unroll
        for (int o = 16; o; o >>= 1) {
            gw += __shfl_xor_sync(0xffffffffu, gw, o);
            bw += __shfl_xor_sync(0xffffffffu, bw, o);
        }
        if (l == 0) { g_GW[w] = gw; g_BW[w] = bw; }
    }
}

// ---------------- LN(x) -> g_xn ----------------
__global__ void __launch_bounds__(192) ln_x_kernel(const float* __restrict__ x,
                                                   const float* __restrict__ g,
                                                   const float* __restrict__ b) {
    int i = blockIdx.x, t = threadIdx.x;
    int c = t * 4;
    float4 xv = *(const float4*)(x + i * 768 + c);
    float s = xv.x + xv.y + xv.z + xv.w;
    float ss = xv.x * xv.x + xv.y * xv.y + xv.z * xv.z + xv.w * xv.w;
    int lane = t & 31, w = t >> 5;
#pragma unroll
    for (int o = 16; o; o >>= 1) {
        s += __shfl_xor_sync(0xffffffffu, s, o);
        ss += __shfl_xor_sync(0xffffffffu, ss, o);
    }
    __shared__ float sh[6][2];
    if (lane == 0) { sh[w][0] = s; sh[w][1] = ss; }
    __syncthreads();
    float S = 0.f, SS = 0.f;
#pragma unroll
    for (int q = 0; q < 6; q++) { S += sh[q][0]; SS += sh[q][1]; }
    float m = S * (1.f / 768.f);
    float r = rsqrtf(SS * (1.f / 768.f) - m * m + EPS);
    float4 gv = *(const float4*)(g + c);
    float4 bv = *(const float4*)(b + c);
    float4 o;
    o.x = (xv.x - m) * r * gv.x + bv.x;
    o.y = (xv.y - m) * r * gv.y + bv.y;
    o.z = (xv.z - m) * r * gv.z + bv.z;
    o.w = (xv.w - m) * r * gv.w + bv.w;
    *(float4*)(g_xn + i * 768 + c) = o;
}

// ---------------- qkv split: QK-LN + head reshapes ----------------
__global__ void __launch_bounds__(192) qkv_prep_kernel(const float* __restrict__ qg,
                                                       const float* __restrict__ qb,
                                                       const float* __restrict__ kg,
                                                       const float* __restrict__ kb) {
    int i = blockIdx.x, p = blockIdx.y, t = threadIdx.x;
    int c = t * 4;
    const float* row = g_qkv + i * 2304 + p * 768;
    float4 xv = *(const float4*)(row + c);
    int h = c >> 6, d = c & 63;
    if (p == 2) {
        *(float4*)(g_vh + (h * 512 + i) * 64 + d) = xv;
        return;
    }
    float s = xv.x + xv.y + xv.z + xv.w;
    float ss = xv.x * xv.x + xv.y * xv.y + xv.z * xv.z + xv.w * xv.w;
    int lane = t & 31, w = t >> 5;
#pragma unroll
    for (int o = 16; o; o >>= 1) {
        s += __shfl_xor_sync(0xffffffffu, s, o);
        ss += __shfl_xor_sync(0xffffffffu, ss, o);
    }
    __shared__ float sh[6][2];
    if (lane == 0) { sh[w][0] = s; sh[w][1] = ss; }
    __syncthreads();
    float S = 0.f, SS = 0.f;
#pragma unroll
    for (int q = 0; q < 6; q++) { S += sh[q][0]; SS += sh[q][1]; }
    float m = S * (1.f / 768.f);
    float r = rsqrtf(SS * (1.f / 768.f) - m * m + EPS);
    const float* gg = (p == 0) ? qg : kg;
    const float* bb = (p == 0) ? qb : kb;
    float4 gv = *(const float4*)(gg + c);
    float4 bv = *(const float4*)(bb + c);
    float v0 = (xv.x - m) * r * gv.x + bv.x;
    float v1 = (xv.y - m) * r * gv.y + bv.y;
    float v2 = (xv.z - m) * r * gv.z + bv.z;
    float v3 = (xv.w - m) * r * gv.w + bv.w;
    if (p == 0) {
        float4 o = make_float4(v0 * 0.125f, v1 * 0.125f, v2 * 0.125f, v3 * 0.125f);
        *(float4*)(g_qh + (h * 512 + i) * 64 + d) = o;
    } else {
        float* kp = g_kT + h * (64 * 512) + d * 512 + i;
        kp[0] = v0; kp[512] = v1; kp[1024] = v2; kp[1536] = v3;
    }
}

// ---------------- pair-bias v7: block-shared staging, row-per-thread ------
// grid (2,512), 256 thr. Thread t owns row j = jt*256 + t (no reductions).
// Per 8-channel chunk: block stages 256 rows x 32B via cp.async (coalesced,
// 2x16B per thread), 3 buffers with 2 chunks in flight; weights from 36KB
// smem as warp-uniform broadcast LDS.128 (pre-packed f32x2); (s,ss) packed.
__global__ void __launch_bounds__(256) pair_bias_kernel(const float* __restrict__ pair) {
    int jt = blockIdx.x, i = blockIdx.y;
    if (jt * 256 > i) return;                  // block-uniform dead exit
    extern __shared__ __align__(16) ull dsm[];
    ull* sgW = dsm;                            // 4608 ull = 36 KB
    float* stg = (float*)(dsm + 4608);         // 3 bufs x 256 rows x 12 floats
    {
        const ull* src = (const ull*)g_gW;
        for (int idx = threadIdx.x; idx < 4608; idx += 256)
            sgW[idx] = src[idx];
    }
    int t = threadIdx.x;
    int j = jt * 256 + t;
    bool live = (j <= i);

    // loader mapping: flat f = p*256 + t -> row f>>1, 16B-seg f&1
    const float* lp[2];
    unsigned int sa[2];
#pragma unroll
    for (int p = 0; p < 2; p++) {
        int f = p * 256 + t;
        int r = f >> 1, seg = f & 1;
        int jr = jt * 256 + r; if (jr > i) jr = i;   // clamp: L2 hits
        lp[p] = pair + ((size_t)i * 512 + jr) * 768 + seg * 4;
        sa[p] = (unsigned int)__cvta_generic_to_shared(stg + r * 12 + seg * 4);
    }
    const unsigned int bufstep = 3072 * 4;     // bytes per buffer

    ull S[6] = {0,0,0,0,0,0};
    ull sss = 0ull;                            // packed (s, ss)

    // prologue: stage chunks 0 and 1
#pragma unroll
    for (int c = 0; c < 2; c++) {
#pragma unroll
        for (int p = 0; p < 2; p++)
            CP_ASYNC16(sa[p] + c * bufstep, lp[p] + c * 8);
        CP_COMMIT();
    }
    __syncthreads();                           // weights ready too

    for (int cc = 0; cc < 96; cc++) {
        if (cc + 2 < 96) {
            unsigned int b = ((cc + 2) % 3) * bufstep;
#pragma unroll
            for (int p = 0; p < 2; p++)
                CP_ASYNC16(sa[p] + b, lp[p] + (cc + 2) * 8);
            CP_COMMIT();
            CP_WAIT2();
        } else if (cc + 1 < 96) {
            CP_WAIT1();
        } else {
            CP_WAIT0();
        }
        __syncthreads();                       // chunk cc visible block-wide
        const float* xr = stg + (cc % 3) * 3072 + t * 12;
        float4 x0 = *(const float4*)xr;
        float4 x1 = *(const float4*)(xr + 4);
        float xs[8] = {x0.x,x0.y,x0.z,x0.w,x1.x,x1.y,x1.z,x1.w};
#pragma unroll
        for (int k = 0; k < 8; k++) {
            const ulonglong2* wp = (const ulonglong2*)&sgW[(cc * 8 + k) * 6];
            ulonglong2 q0 = wp[0];
            ulonglong2 q1 = wp[1];
            ulonglong2 q2 = wp[2];
            float x = xs[k];
            ull xx = pk2(x, x);
            ull ox = pk2(1.0f, x);
            sss = fma2(xx, ox, sss);           // (s += x, ss += x*x)
            S[0] = fma2(xx, q0.x, S[0]);
            S[1] = fma2(xx, q0.y, S[1]);
            S[2] = fma2(xx, q1.x, S[2]);
            S[3] = fma2(xx, q1.y, S[3]);
            S[4] = fma2(xx, q2.x, S[4]);
            S[5] = fma2(xx, q2.y, S[5]);
        }
        __syncthreads();                       // all done with buf cc%3
    }

    if (!live) return;
    float s, ss; unpk2(s, ss, sss);
    float m = s * (1.f / 768.f);
    float r = rsqrtf(ss * (1.f / 768.f) - m * m + EPS);
    size_t pos = (size_t)i * 512 + j;
#pragma unroll
    for (int h2 = 0; h2 < 6; h2++) {
        float lo, hi; unpk2(lo, hi, S[h2]);
        g_bias[(size_t)(2 * h2) * (512 * 512) + pos] =
            r * (lo - m * __ldg(&g_GW[2 * h2])) + __ldg(&g_BW[2 * h2]);
        g_bias[(size_t)(2 * h2 + 1) * (512 * 512) + pos] =
            r * (hi - m * __ldg(&g_GW[2 * h2 + 1])) + __ldg(&g_BW[2 * h2 + 1]);
    }
}

// ---------------- f32x2 GEMM (R6 known-good): N-packed acc, double-buffered
template <int BM, int BN, int TM, int TN>
__device__ __forceinline__ void gemm2_body(const float* __restrict__ A,
                                           const float* __restrict__ B,
                                           float* __restrict__ C,
                                           const float* __restrict__ biasRow,
                                           const float* __restrict__ biasMat,
                                           int K, int lda, int ldb, int ldc) {
    constexpr int THREADS = (BM / TM) * (BN / TN);
    static_assert(THREADS == 256 && TM == 4, "shape");
    __shared__ __align__(16) float As[2][8][BM];
    __shared__ __align__(16) float Bs[2][8][BN];

    int tid = threadIdx.x;
    int tx = tid % (BN / TN), ty = tid / (BN / TN);
    int m0 = blockIdx.y * BM, n0 = blockIdx.x * BN;

    ull acc[TM][TN / 2];
#pragma unroll
    for (int ii = 0; ii < TM; ii++)
#pragma unroll
        for (int j2 = 0; j2 < TN / 2; j2++) acc[ii][j2] = 0ull;

    bool aact = tid < 2 * BM;
    bool bact = tid < 2 * BN;
    int ar = tid >> 1, ac = (tid & 1) * 4;
    int br = tid / (BN / 4), bc = (tid % (BN / 4)) * 4;

    float4 pa = make_float4(0.f, 0.f, 0.f, 0.f), pb = pa;
    if (aact) pa = *(const float4*)(A + (size_t)(m0 + ar) * lda + ac);
    if (bact) pb = *(const float4*)(B + (size_t)br * ldb + n0 + bc);
    if (aact) {
        As[0][ac + 0][ar] = pa.x; As[0][ac + 1][ar] = pa.y;
        As[0][ac + 2][ar] = pa.z; As[0][ac + 3][ar] = pa.w;
    }
    if (bact) *(float4*)&Bs[0][br][bc] = pb;
    __syncthreads();

    int sb = 0;
    for (int k0 = 0; k0 < K; k0 += 8) {
        bool more = (k0 + 8 < K);
        if (more) {
            if (aact) pa = *(const float4*)(A + (size_t)(m0 + ar) * lda + k0 + 8 + ac);
            if (bact) pb = *(const float4*)(B + (size_t)(k0 + 8 + br) * ldb + n0 + bc);
        }
#pragma unroll
        for (int kk = 0; kk < 8; kk++) {
            float4 av = *(const float4*)&As[sb][kk][ty * TM];
            float a4[4] = {av.x, av.y, av.z, av.w};
            ull b2[TN / 2];
            const ull* bp = (const ull*)&Bs[sb][kk][tx * TN];
#pragma unroll
            for (int j2 = 0; j2 < TN / 2; j2++) b2[j2] = bp[j2];
#pragma unroll
            for (int ii = 0; ii < TM; ii++) {
                ull aa = pk2(a4[ii], a4[ii]);
#pragma unroll
                for (int j2 = 0; j2 < TN / 2; j2++)
                    acc[ii][j2] = fma2(aa, b2[j2], acc[ii][j2]);
            }
        }
        if (more) {
            if (aact) {
                As[sb ^ 1][ac + 0][ar] = pa.x; As[sb ^ 1][ac + 1][ar] = pa.y;
                As[sb ^ 1][ac + 2][ar] = pa.z; As[sb ^ 1][ac + 3][ar] = pa.w;
            }
            if (bact) *(float4*)&Bs[sb ^ 1][br][bc] = pb;
            __syncthreads();
            sb ^= 1;
        }
    }

    float bv[TN];
#pragma unroll
    for (int c = 0; c < TN; c++)
        bv[c] = biasRow ? biasRow[n0 + tx * TN + c] : 0.f;

#pragma unroll
    for (int ii = 0; ii < TM; ii++) {
        int r = m0 + ty * TM + ii;
        float o[TN];
#pragma unroll
        for (int j2 = 0; j2 < TN / 2; j2++) {
            unpk2(o[2 * j2], o[2 * j2 + 1], acc[ii][j2]);
            o[2 * j2] += bv[2 * j2];
            o[2 * j2 + 1] += bv[2 * j2 + 1];
        }
        if (biasMat) {
            const float* bm = biasMat + (size_t)r * ldc + n0 + tx * TN;
#pragma unroll
            for (int c4 = 0; c4 < TN / 4; c4++) {
                float4 mv = *(const float4*)(bm + 4 * c4);
                o[4*c4+0] += mv.x; o[4*c4+1] += mv.y;
                o[4*c4+2] += mv.z; o[4*c4+3] += mv.w;
            }
        }
        float* cp = C + (size_t)r * ldc + n0 + tx * TN;
#pragma unroll
        for (int c4 = 0; c4 < TN / 4; c4++)
            *(float4*)(cp + 4 * c4) = make_float4(o[4*c4], o[4*c4+1], o[4*c4+2], o[4*c4+3]);
    }
}

__global__ void __launch_bounds__(256) gemm_qkv(const float* __restrict__ W,
                                                const float* __restrict__ bias) {
    gemm2_body<64, 64, 4, 4>(g_xn, W, g_qkv, bias, nullptr, 768, 768, 2304, 2304);
}
__global__ void __launch_bounds__(256) gemm_qk() {
    int h = blockIdx.z;
    gemm2_body<64, 128, 4, 8>(g_qh + h * (512 * 64), g_kT + h * (64 * 512),
                              g_sim + (size_t)h * (512 * 512), nullptr,
                              g_bias + (size_t)h * (512 * 512), 64, 64, 512, 512);
}
__global__ void __launch_bounds__(256) gemm_pv() {
    int h = blockIdx.z;
    gemm2_body<64, 64, 4, 4>(g_sim + (size_t)h * (512 * 512), g_vh + h * (512 * 64),
                             g_attout + h * 64, nullptr, nullptr, 512, 512, 64, 768);
}
__global__ void __launch_bounds__(256) gemm_proj(const float* __restrict__ W,
                                                 const float* __restrict__ bias,
                                                 float* __restrict__ out) {
    gemm2_body<64, 64, 4, 4>(g_attout, W, out, bias, nullptr, 768, 768, 768, 768);
}

// ---------------- softmax: warp per (h,i) row, registers only ----------------
__global__ void __launch_bounds__(256) softmax_kernel() {
    int warp = threadIdx.x >> 5, lane = threadIdx.x & 31;
    int rowid = blockIdx.x * 8 + warp;              // 0..6143
    float* row = g_sim + (size_t)rowid * 512;
    float v[16];
    float4* rp = (float4*)(row + lane * 16);
    float4 r0 = rp[0], r1 = rp[1], r2 = rp[2], r3 = rp[3];
    v[0]=r0.x; v[1]=r0.y; v[2]=r0.z; v[3]=r0.w;
    v[4]=r1.x; v[5]=r1.y; v[6]=r1.z; v[7]=r1.w;
    v[8]=r2.x; v[9]=r2.y; v[10]=r2.z; v[11]=r2.w;
    v[12]=r3.x; v[13]=r3.y; v[14]=r3.z; v[15]=r3.w;
    float m = v[0];
#pragma unroll
    for (int e = 1; e < 16; e++) m = fmaxf(m, v[e]);
#pragma unroll
    for (int o = 16; o; o >>= 1) m = fmaxf(m, __shfl_xor_sync(0xffffffffu, m, o));
    float s = 0.f;
#pragma unroll
    for (int e = 0; e < 16; e++) { v[e] = __expf(v[e] - m); s += v[e]; }
#pragma unroll
    for (int o = 16; o; o >>= 1) s += __shfl_xor_sync(0xffffffffu, s, o);
    float inv = __fdividef(1.f, s);
    rp[0] = make_float4(v[0]*inv, v[1]*inv, v[2]*inv, v[3]*inv);
    rp[1] = make_float4(v[4]*inv, v[5]*inv, v[6]*inv, v[7]*inv);
    rp[2] = make_float4(v[8]*inv, v[9]*inv, v[10]*inv, v[11]*inv);
    rp[3] = make_float4(v[12]*inv, v[13]*inv, v[14]*inv, v[15]*inv);
}

// ---------------- launch ----------------
extern "C" void kernel_launch(void* const* d_in, const int* in_sizes, int n_in,
                              void* d_out, int out_size) {
    int base = n_in - 13;                     // norm_g index (mask-type agnostic)
    const float* x      = (const float*)d_in[0];
    const float* pair   = (const float*)d_in[1];
    const float* norm_g = (const float*)d_in[base + 0];
    const float* norm_b = (const float*)d_in[base + 1];
    const float* Wqkv   = (const float*)d_in[base + 2];
    const float* bqkv   = (const float*)d_in[base + 3];
    const float* qln_g  = (const float*)d_in[base + 4];
    const float* qln_b  = (const float*)d_in[base + 5];
    const float* kln_g  = (const float*)d_in[base + 6];
    const float* kln_b  = (const float*)d_in[base + 7];
    const float* pair_g = (const float*)d_in[base + 8];
    const float* pair_b = (const float*)d_in[base + 9];
    const float* Wbias  = (const float*)d_in[base + 10];
    const float* Wproj  = (const float*)d_in[base + 11];
    const float* bproj  = (const float*)d_in[base + 12];
    float* out = (float*)d_out;

    const int PB_SMEM = 4608 * 8 + 3 * 3072 * 4;   // 36KB weights + 36KB staging
    cudaFuncSetAttribute(pair_bias_kernel,
                         cudaFuncAttributeMaxDynamicSharedMemorySize, PB_SMEM);

    precompute_gw<<<1, 384>>>(pair_g, pair_b, Wbias);              // 1
    ln_x_kernel<<<512, 192>>>(x, norm_g, norm_b);                  // 2
    gemm_qkv<<<dim3(36, 8), 256>>>(Wqkv, bqkv);                    // 3
    pair_bias_kernel<<<dim3(2, 512), 256, PB_SMEM>>>(pair);        // 4 <- profiled
    qkv_prep_kernel<<<dim3(512, 3), 192>>>(qln_g, qln_b, kln_g, kln_b); // 5
    gemm_qk<<<dim3(4, 8, 12), 256>>>();                            // 6
    softmax_kernel<<<768, 256>>>();                                // 7
    gemm_pv<<<dim3(1, 8, 12), 256>>>();                            // 8
    gemm_proj<<<dim3(12, 8), 256>>>(Wproj, bproj, out);            // 9
}

// round 15
// speedup vs baseline: 1.3740x; 1.3740x over previous
#include <cuda_runtime.h>
#include <cstdint>
#include <math.h>

#define EPS 1e-5f
typedef unsigned long long ull;

// ---------------- f32x2 packed helpers ----------------
__device__ __forceinline__ ull pk2(float lo, float hi) {
    ull r; asm("mov.b64 %0,{%1,%2};" : "=l"(r) : "f"(lo), "f"(hi)); return r;
}
__device__ __forceinline__ void unpk2(float& lo, float& hi, ull v) {
    asm("mov.b64 {%0,%1},%2;" : "=f"(lo), "=f"(hi) : "l"(v));
}
__device__ __forceinline__ ull fma2(ull a, ull b, ull c) {
    ull d; asm("fma.rn.f32x2 %0,%1,%2,%3;" : "=l"(d) : "l"(a), "l"(b), "l"(c)); return d;
}
#define CP_ASYNC16(dst, src) \
    asm volatile("cp.async.ca.shared.global [%0], [%1], 16;" :: "r"(dst), "l"(src))
#define CP_COMMIT() asm volatile("cp.async.commit_group;" ::: "memory")
#define CP_WAIT1() asm volatile("cp.async.wait_group 1;" ::: "memory")
#define CP_WAIT0() asm volatile("cp.async.wait_group 0;" ::: "memory")

// ---------------- scratch (device globals; no allocations) ----------------
__device__ float g_xn[512 * 768];
__device__ float g_qkv[512 * 2304];
__device__ float g_qh[12 * 512 * 64];    // [h][i][d], q * scale
__device__ float g_kT[12 * 64 * 512];    // [h][d][j]
__device__ float g_vh[12 * 512 * 64];    // [h][j][d]
__device__ __align__(16) float g_gW[768 * 12];  // pair_g[c] * Wbias[c][h]
__device__ float g_GW[12];
__device__ float g_BW[12];
__device__ float g_bias[12 * 512 * 512]; // [h][i][j]; j>i stays 0 (.bss)
__device__ float g_sim[12 * 512 * 512];  // [h][i][j], reused as attn
__device__ float g_attout[512 * 768];    // [i][h*64+d]

// ---------------- precompute gW, GW, BW ----------------
__global__ void precompute_gw(const float* __restrict__ pg,
                              const float* __restrict__ pb,
                              const float* __restrict__ Wb) {
    int t = threadIdx.x; // 384
    for (int idx = t; idx < 768 * 12; idx += 384)
        g_gW[idx] = pg[idx / 12] * Wb[idx];
    int w = t >> 5, l = t & 31;
    if (w < 12) {
        float gw = 0.f, bw = 0.f;
        for (int c = l; c < 768; c += 32) {
            float wv = Wb[c * 12 + w];
            gw = fmaf(pg[c], wv, gw);
            bw = fmaf(pb[c], wv, bw);
        }
#pragma unroll
        for (int o = 16; o; o >>= 1) {
            gw += __shfl_xor_sync(0xffffffffu, gw, o);
            bw += __shfl_xor_sync(0xffffffffu, bw, o);
        }
        if (l == 0) { g_GW[w] = gw; g_BW[w] = bw; }
    }
}

// ---------------- LN(x) -> g_xn ----------------
__global__ void __launch_bounds__(192) ln_x_kernel(const float* __restrict__ x,
                                                   const float* __restrict__ g,
                                                   const float* __restrict__ b) {
    int i = blockIdx.x, t = threadIdx.x;
    int c = t * 4;
    float4 xv = *(const float4*)(x + i * 768 + c);
    float s = xv.x + xv.y + xv.z + xv.w;
    float ss = xv.x * xv.x + xv.y * xv.y + xv.z * xv.z + xv.w * xv.w;
    int lane = t & 31, w = t >> 5;
#pragma unroll
    for (int o = 16; o; o >>= 1) {
        s += __shfl_xor_sync(0xffffffffu, s, o);
        ss += __shfl_xor_sync(0xffffffffu, ss, o);
    }
    __shared__ float sh[6][2];
    if (lane == 0) { sh[w][0] = s; sh[w][1] = ss; }
    __syncthreads();
    float S = 0.f, SS = 0.f;
#pragma unroll
    for (int q = 0; q < 6; q++) { S += sh[q][0]; SS += sh[q][1]; }
    float m = S * (1.f / 768.f);
    float r = rsqrtf(SS * (1.f / 768.f) - m * m + EPS);
    float4 gv = *(const float4*)(g + c);
    float4 bv = *(const float4*)(b + c);
    float4 o;
    o.x = (xv.x - m) * r * gv.x + bv.x;
    o.y = (xv.y - m) * r * gv.y + bv.y;
    o.z = (xv.z - m) * r * gv.z + bv.z;
    o.w = (xv.w - m) * r * gv.w + bv.w;
    *(float4*)(g_xn + i * 768 + c) = o;
}

// ---------------- qkv split: QK-LN + head reshapes ----------------
__global__ void __launch_bounds__(192) qkv_prep_kernel(const float* __restrict__ qg,
                                                       const float* __restrict__ qb,
                                                       const float* __restrict__ kg,
                                                       const float* __restrict__ kb) {
    int i = blockIdx.x, p = blockIdx.y, t = threadIdx.x;
    int c = t * 4;
    const float* row = g_qkv + i * 2304 + p * 768;
    float4 xv = *(const float4*)(row + c);
    int h = c >> 6, d = c & 63;
    if (p == 2) {
        *(float4*)(g_vh + (h * 512 + i) * 64 + d) = xv;
        return;
    }
    float s = xv.x + xv.y + xv.z + xv.w;
    float ss = xv.x * xv.x + xv.y * xv.y + xv.z * xv.z + xv.w * xv.w;
    int lane = t & 31, w = t >> 5;
#pragma unroll
    for (int o = 16; o; o >>= 1) {
        s += __shfl_xor_sync(0xffffffffu, s, o);
        ss += __shfl_xor_sync(0xffffffffu, ss, o);
    }
    __shared__ float sh[6][2];
    if (lane == 0) { sh[w][0] = s; sh[w][1] = ss; }
    __syncthreads();
    float S = 0.f, SS = 0.f;
#pragma unroll
    for (int q = 0; q < 6; q++) { S += sh[q][0]; SS += sh[q][1]; }
    float m = S * (1.f / 768.f);
    float r = rsqrtf(SS * (1.f / 768.f) - m * m + EPS);
    const float* gg = (p == 0) ? qg : kg;
    const float* bb = (p == 0) ? qb : kb;
    float4 gv = *(const float4*)(gg + c);
    float4 bv = *(const float4*)(bb + c);
    float v0 = (xv.x - m) * r * gv.x + bv.x;
    float v1 = (xv.y - m) * r * gv.y + bv.y;
    float v2 = (xv.z - m) * r * gv.z + bv.z;
    float v3 = (xv.w - m) * r * gv.w + bv.w;
    if (p == 0) {
        float4 o = make_float4(v0 * 0.125f, v1 * 0.125f, v2 * 0.125f, v3 * 0.125f);
        *(float4*)(g_qh + (h * 512 + i) * 64 + d) = o;
    } else {
        float* kp = g_kT + h * (64 * 512) + d * 512 + i;
        kp[0] = v0; kp[512] = v1; kp[1024] = v2; kp[1536] = v3;
    }
}

// ---------------- pair-bias v8: 32-ch chunks, warp-private pipeline -------
// grid (2,512), 256 thr = 8 warps. Warp w owns rows jw..jw+31, lane owns one
// row (no reductions). Per 32-channel chunk (4KB/warp): 8 cp.async warp-instr
// (full 128B lines, 4 rows each), 2 buffers with 1 chunk always in flight
// during compute. No row clamping: over-diagonal reads are in-bounds garbage,
// discarded by dead lanes. Weights: 36KB smem, warp-uniform LDS.128 of
// pre-packed f32x2 pairs. Staging stride 36 floats -> conflict-free LDS.128.
__global__ void __launch_bounds__(256) pair_bias_kernel(const float* __restrict__ pair) {
    int jt = blockIdx.x, i = blockIdx.y;
    if (jt * 256 > i) return;                  // block-uniform dead exit
    extern __shared__ __align__(16) ull dsm[];
    ull* sgW = dsm;                            // 4608 ull = 36 KB
    float* stg = (float*)(dsm + 4608);         // 8 warps x 2 bufs x 1152 floats
    {
        const ull* src = (const ull*)g_gW;
        for (int idx = threadIdx.x; idx < 4608; idx += 256)
            sgW[idx] = src[idx];
    }
    __syncthreads();

    int w = threadIdx.x >> 5, lane = threadIdx.x & 31;
    int jw = jt * 256 + w * 32;
    if (jw > i) return;                        // dead warp (after the sync)
    int j = jw + lane;
    bool live = (j <= i);

    // loader: task f = p*32+lane -> row (lane>>3)+4p, seg lane&7 (16B)
    // single base + uniform offsets (p: +4*768 floats; chunk: +32 floats)
    const float* gsrc = pair + ((size_t)i * 512 + jw + (lane >> 3)) * 768 + (lane & 7) * 4;
    float* bufq = stg + w * 2304;              // 2 bufs x 1152 floats
    unsigned int sdst = (unsigned int)__cvta_generic_to_shared(
        bufq + (lane >> 3) * 36 + (lane & 7) * 4);
    const unsigned int BUFB = 1152 * 4;        // bytes per buffer
    const unsigned int PSTP = 4 * 36 * 4;      // bytes per p-step (4 rows)

    ull S[6] = {0,0,0,0,0,0};
    ull sss = 0ull;                            // packed (s, ss)

    // prologue: chunks 0 (buf0) and 1 (buf1)
#pragma unroll
    for (int c = 0; c < 2; c++) {
#pragma unroll
        for (int p = 0; p < 8; p++)
            CP_ASYNC16(sdst + c * BUFB + p * PSTP, gsrc + c * 32 + (size_t)p * 4 * 768);
        CP_COMMIT();
    }

    for (int cc = 0; cc < 24; cc++) {
        if (cc < 23) { CP_WAIT1(); } else { CP_WAIT0(); }
        __syncwarp();                          // all lanes' chunk-cc copies visible
        const float* xr = bufq + (cc & 1) * 1152 + lane * 36;
#pragma unroll
        for (int q = 0; q < 8; q++) {
            float4 xv = *(const float4*)(xr + q * 4);
            float xs[4] = {xv.x, xv.y, xv.z, xv.w};
#pragma unroll
            for (int k = 0; k < 4; k++) {
                int ch = cc * 32 + q * 4 + k;
                const ulonglong2* wp = (const ulonglong2*)&sgW[ch * 6];
                ulonglong2 q0 = wp[0];
                ulonglong2 q1 = wp[1];
                ulonglong2 q2 = wp[2];
                float x = xs[k];
                ull xx = pk2(x, x);
                sss = fma2(xx, pk2(1.0f, x), sss);
                S[0] = fma2(xx, q0.x, S[0]);
                S[1] = fma2(xx, q0.y, S[1]);
                S[2] = fma2(xx, q1.x, S[2]);
                S[3] = fma2(xx, q1.y, S[3]);
                S[4] = fma2(xx, q2.x, S[4]);
                S[5] = fma2(xx, q2.y, S[5]);
            }
        }
        __syncwarp();                          // compute done before buf reuse
        if (cc + 2 < 24) {                     // refill the buffer just freed
#pragma unroll
            for (int p = 0; p < 8; p++)
                CP_ASYNC16(sdst + (cc & 1) * BUFB + p * PSTP,
                           gsrc + (cc + 2) * 32 + (size_t)p * 4 * 768);
            CP_COMMIT();
        }
    }

    if (!live) return;
    float s, ss; unpk2(s, ss, sss);
    float m = s * (1.f / 768.f);
    float r = rsqrtf(ss * (1.f / 768.f) - m * m + EPS);
    size_t pos = (size_t)i * 512 + j;
#pragma unroll
    for (int h2 = 0; h2 < 6; h2++) {
        float lo, hi; unpk2(lo, hi, S[h2]);
        g_bias[(size_t)(2 * h2) * (512 * 512) + pos] =
            r * (lo - m * __ldg(&g_GW[2 * h2])) + __ldg(&g_BW[2 * h2]);
        g_bias[(size_t)(2 * h2 + 1) * (512 * 512) + pos] =
            r * (hi - m * __ldg(&g_GW[2 * h2 + 1])) + __ldg(&g_BW[2 * h2 + 1]);
    }
}

// ---------------- f32x2 GEMM (R6 known-good): N-packed acc, double-buffered
template <int BM, int BN, int TM, int TN>
__device__ __forceinline__ void gemm2_body(const float* __restrict__ A,
                                           const float* __restrict__ B,
                                           float* __restrict__ C,
                                           const float* __restrict__ biasRow,
                                           const float* __restrict__ biasMat,
                                           int K, int lda, int ldb, int ldc) {
    constexpr int THREADS = (BM / TM) * (BN / TN);
    static_assert(THREADS == 256 && TM == 4, "shape");
    __shared__ __align__(16) float As[2][8][BM];
    __shared__ __align__(16) float Bs[2][8][BN];

    int tid = threadIdx.x;
    int tx = tid % (BN / TN), ty = tid / (BN / TN);
    int m0 = blockIdx.y * BM, n0 = blockIdx.x * BN;

    ull acc[TM][TN / 2];
#pragma unroll
    for (int ii = 0; ii < TM; ii++)
#pragma unroll
        for (int j2 = 0; j2 < TN / 2; j2++) acc[ii][j2] = 0ull;

    bool aact = tid < 2 * BM;
    bool bact = tid < 2 * BN;
    int ar = tid >> 1, ac = (tid & 1) * 4;
    int br = tid / (BN / 4), bc = (tid % (BN / 4)) * 4;

    float4 pa = make_float4(0.f, 0.f, 0.f, 0.f), pb = pa;
    if (aact) pa = *(const float4*)(A + (size_t)(m0 + ar) * lda + ac);
    if (bact) pb = *(const float4*)(B + (size_t)br * ldb + n0 + bc);
    if (aact) {
        As[0][ac + 0][ar] = pa.x; As[0][ac + 1][ar] = pa.y;
        As[0][ac + 2][ar] = pa.z; As[0][ac + 3][ar] = pa.w;
    }
    if (bact) *(float4*)&Bs[0][br][bc] = pb;
    __syncthreads();

    int sb = 0;
    for (int k0 = 0; k0 < K; k0 += 8) {
        bool more = (k0 + 8 < K);
        if (more) {
            if (aact) pa = *(const float4*)(A + (size_t)(m0 + ar) * lda + k0 + 8 + ac);
            if (bact) pb = *(const float4*)(B + (size_t)(k0 + 8 + br) * ldb + n0 + bc);
        }
#pragma unroll
        for (int kk = 0; kk < 8; kk++) {
            float4 av = *(const float4*)&As[sb][kk][ty * TM];
            float a4[4] = {av.x, av.y, av.z, av.w};
            ull b2[TN / 2];
            const ull* bp = (const ull*)&Bs[sb][kk][tx * TN];
#pragma unroll
            for (int j2 = 0; j2 < TN / 2; j2++) b2[j2] = bp[j2];
#pragma unroll
            for (int ii = 0; ii < TM; ii++) {
                ull aa = pk2(a4[ii], a4[ii]);
#pragma unroll
                for (int j2 = 0; j2 < TN / 2; j2++)
                    acc[ii][j2] = fma2(aa, b2[j2], acc[ii][j2]);
            }
        }
        if (more) {
            if (aact) {
                As[sb ^ 1][ac + 0][ar] = pa.x; As[sb ^ 1][ac + 1][ar] = pa.y;
                As[sb ^ 1][ac + 2][ar] = pa.z; As[sb ^ 1][ac + 3][ar] = pa.w;
            }
            if (bact) *(float4*)&Bs[sb ^ 1][br][bc] = pb;
            __syncthreads();
            sb ^= 1;
        }
    }

    float bv[TN];
#pragma unroll
    for (int c = 0; c < TN; c++)
        bv[c] = biasRow ? biasRow[n0 + tx * TN + c] : 0.f;

#pragma unroll
    for (int ii = 0; ii < TM; ii++) {
        int r = m0 + ty * TM + ii;
        float o[TN];
#pragma unroll
        for (int j2 = 0; j2 < TN / 2; j2++) {
            unpk2(o[2 * j2], o[2 * j2 + 1], acc[ii][j2]);
            o[2 * j2] += bv[2 * j2];
            o[2 * j2 + 1] += bv[2 * j2 + 1];
        }
        if (biasMat) {
            const float* bm = biasMat + (size_t)r * ldc + n0 + tx * TN;
#pragma unroll
            for (int c4 = 0; c4 < TN / 4; c4++) {
                float4 mv = *(const float4*)(bm + 4 * c4);
                o[4*c4+0] += mv.x; o[4*c4+1] += mv.y;
                o[4*c4+2] += mv.z; o[4*c4+3] += mv.w;
            }
        }
        float* cp = C + (size_t)r * ldc + n0 + tx * TN;
#pragma unroll
        for (int c4 = 0; c4 < TN / 4; c4++)
            *(float4*)(cp + 4 * c4) = make_float4(o[4*c4], o[4*c4+1], o[4*c4+2], o[4*c4+3]);
    }
}

__global__ void __launch_bounds__(256) gemm_qkv(const float* __restrict__ W,
                                                const float* __restrict__ bias) {
    gemm2_body<64, 64, 4, 4>(g_xn, W, g_qkv, bias, nullptr, 768, 768, 2304, 2304);
}
__global__ void __launch_bounds__(256) gemm_qk() {
    int h = blockIdx.z;
    gemm2_body<64, 128, 4, 8>(g_qh + h * (512 * 64), g_kT + h * (64 * 512),
                              g_sim + (size_t)h * (512 * 512), nullptr,
                              g_bias + (size_t)h * (512 * 512), 64, 64, 512, 512);
}
__global__ void __launch_bounds__(256) gemm_pv() {
    int h = blockIdx.z;
    gemm2_body<64, 64, 4, 4>(g_sim + (size_t)h * (512 * 512), g_vh + h * (512 * 64),
                             g_attout + h * 64, nullptr, nullptr, 512, 512, 64, 768);
}
__global__ void __launch_bounds__(256) gemm_proj(const float* __restrict__ W,
                                                 const float* __restrict__ bias,
                                                 float* __restrict__ out) {
    gemm2_body<64, 64, 4, 4>(g_attout, W, out, bias, nullptr, 768, 768, 768, 768);
}

// ---------------- softmax: warp per (h,i) row, registers only ----------------
__global__ void __launch_bounds__(256) softmax_kernel() {
    int warp = threadIdx.x >> 5, lane = threadIdx.x & 31;
    int rowid = blockIdx.x * 8 + warp;              // 0..6143
    float* row = g_sim + (size_t)rowid * 512;
    float v[16];
    float4* rp = (float4*)(row + lane * 16);
    float4 r0 = rp[0], r1 = rp[1], r2 = rp[2], r3 = rp[3];
    v[0]=r0.x; v[1]=r0.y; v[2]=r0.z; v[3]=r0.w;
    v[4]=r1.x; v[5]=r1.y; v[6]=r1.z; v[7]=r1.w;
    v[8]=r2.x; v[9]=r2.y; v[10]=r2.z; v[11]=r2.w;
    v[12]=r3.x; v[13]=r3.y; v[14]=r3.z; v[15]=r3.w;
    float m = v[0];
#pragma unroll
    for (int e = 1; e < 16; e++) m = fmaxf(m, v[e]);
#pragma unroll
    for (int o = 16; o; o >>= 1) m = fmaxf(m, __shfl_xor_sync(0xffffffffu, m, o));
    float s = 0.f;
#pragma unroll
    for (int e = 0; e < 16; e++) { v[e] = __expf(v[e] - m); s += v[e]; }
#pragma unroll
    for (int o = 16; o; o >>= 1) s += __shfl_xor_sync(0xffffffffu, s, o);
    float inv = __fdividef(1.f, s);
    rp[0] = make_float4(v[0]*inv, v[1]*inv, v[2]*inv, v[3]*inv);
    rp[1] = make_float4(v[4]*inv, v[5]*inv, v[6]*inv, v[7]*inv);
    rp[2] = make_float4(v[8]*inv, v[9]*inv, v[10]*inv, v[11]*inv);
    rp[3] = make_float4(v[12]*inv, v[13]*inv, v[14]*inv, v[15]*inv);
}

// ---------------- launch ----------------
extern "C" void kernel_launch(void* const* d_in, const int* in_sizes, int n_in,
                              void* d_out, int out_size) {
    int base = n_in - 13;                     // norm_g index (mask-type agnostic)
    const float* x      = (const float*)d_in[0];
    const float* pair   = (const float*)d_in[1];
    const float* norm_g = (const float*)d_in[base + 0];
    const float* norm_b = (const float*)d_in[base + 1];
    const float* Wqkv   = (const float*)d_in[base + 2];
    const float* bqkv   = (const float*)d_in[base + 3];
    const float* qln_g  = (const float*)d_in[base + 4];
    const float* qln_b  = (const float*)d_in[base + 5];
    const float* kln_g  = (const float*)d_in[base + 6];
    const float* kln_b  = (const float*)d_in[base + 7];
    const float* pair_g = (const float*)d_in[base + 8];
    const float* pair_b = (const float*)d_in[base + 9];
    const float* Wbias  = (const float*)d_in[base + 10];
    const float* Wproj  = (const float*)d_in[base + 11];
    const float* bproj  = (const float*)d_in[base + 12];
    float* out = (float*)d_out;

    const int PB_SMEM = 4608 * 8 + 8 * 2 * 1152 * 4;   // 36KB weights + 72KB staging
    cudaFuncSetAttribute(pair_bias_kernel,
                         cudaFuncAttributeMaxDynamicSharedMemorySize, PB_SMEM);

    precompute_gw<<<1, 384>>>(pair_g, pair_b, Wbias);              // 1
    ln_x_kernel<<<512, 192>>>(x, norm_g, norm_b);                  // 2
    gemm_qkv<<<dim3(36, 8), 256>>>(Wqkv, bqkv);                    // 3
    pair_bias_kernel<<<dim3(2, 512), 256, PB_SMEM>>>(pair);        // 4 <- profiled
    qkv_prep_kernel<<<dim3(512, 3), 192>>>(qln_g, qln_b, kln_g, kln_b); // 5
    gemm_qk<<<dim3(4, 8, 12), 256>>>();                            // 6
    softmax_kernel<<<768, 256>>>();                                // 7
    gemm_pv<<<dim3(1, 8, 12), 256>>>();                            // 8
    gemm_proj<<<dim3(12, 8), 256>>>(Wproj, bproj, out);            // 9
}

// round 16
// speedup vs baseline: 1.6066x; 1.1693x over previous
#include <cuda_runtime.h>
#include <cstdint>
#include <math.h>

#define EPS 1e-5f
typedef unsigned long long ull;

// ---------------- f32x2 packed helpers ----------------
__device__ __forceinline__ ull pk2(float lo, float hi) {
    ull r; asm("mov.b64 %0,{%1,%2};" : "=l"(r) : "f"(lo), "f"(hi)); return r;
}
__device__ __forceinline__ void unpk2(float& lo, float& hi, ull v) {
    asm("mov.b64 {%0,%1},%2;" : "=f"(lo), "=f"(hi) : "l"(v));
}
__device__ __forceinline__ ull fma2(ull a, ull b, ull c) {
    ull d; asm("fma.rn.f32x2 %0,%1,%2,%3;" : "=l"(d) : "l"(a), "l"(b), "l"(c)); return d;
}
#define CP_ASYNC16CG(dst, src) \
    asm volatile("cp.async.cg.shared.global [%0], [%1], 16;" :: "r"(dst), "l"(src))
#define CP_ASYNC16(dst, src) \
    asm volatile("cp.async.ca.shared.global [%0], [%1], 16;" :: "r"(dst), "l"(src))
#define CP_COMMIT() asm volatile("cp.async.commit_group;" ::: "memory")
#define CP_WAIT1() asm volatile("cp.async.wait_group 1;" ::: "memory")
#define CP_WAIT0() asm volatile("cp.async.wait_group 0;" ::: "memory")

// ---------------- scratch (device globals; no allocations) ----------------
__device__ float g_xn[512 * 768];
__device__ float g_qkv[512 * 2304];
__device__ float g_qh[12 * 512 * 64];    // [h][i][d], q * scale
__device__ float g_kT[12 * 64 * 512];    // [h][d][j]
__device__ float g_vh[12 * 512 * 64];    // [h][j][d]
__device__ __align__(16) float g_gW[768 * 12];  // pair_g[c] * Wbias[c][h]
__device__ float g_GW[12];
__device__ float g_BW[12];
__device__ float g_bias[12 * 512 * 512]; // [h][i][j]; j>i stays 0 (.bss)
__device__ float g_sim[12 * 512 * 512];  // [h][i][j], reused as attn
__device__ float g_attout[512 * 768];    // [i][h*64+d]

// ---------------- precompute gW, GW, BW ----------------
__global__ void precompute_gw(const float* __restrict__ pg,
                              const float* __restrict__ pb,
                              const float* __restrict__ Wb) {
    int t = threadIdx.x; // 384
    for (int idx = t; idx < 768 * 12; idx += 384)
        g_gW[idx] = pg[idx / 12] * Wb[idx];
    int w = t >> 5, l = t & 31;
    if (w < 12) {
        float gw = 0.f, bw = 0.f;
        for (int c = l; c < 768; c += 32) {
            float wv = Wb[c * 12 + w];
            gw = fmaf(pg[c], wv, gw);
            bw = fmaf(pb[c], wv, bw);
        }
#pragma unroll
        for (int o = 16; o; o >>= 1) {
            gw += __shfl_xor_sync(0xffffffffu, gw, o);
            bw += __shfl_xor_sync(0xffffffffu, bw, o);
        }
        if (l == 0) { g_GW[w] = gw; g_BW[w] = bw; }
    }
}

// ---------------- LN(x) -> g_xn ----------------
__global__ void __launch_bounds__(192) ln_x_kernel(const float* __restrict__ x,
                                                   const float* __restrict__ g,
                                                   const float* __restrict__ b) {
    int i = blockIdx.x, t = threadIdx.x;
    int c = t * 4;
    float4 xv = *(const float4*)(x + i * 768 + c);
    float s = xv.x + xv.y + xv.z + xv.w;
    float ss = xv.x * xv.x + xv.y * xv.y + xv.z * xv.z + xv.w * xv.w;
    int lane = t & 31, w = t >> 5;
#pragma unroll
    for (int o = 16; o; o >>= 1) {
        s += __shfl_xor_sync(0xffffffffu, s, o);
        ss += __shfl_xor_sync(0xffffffffu, ss, o);
    }
    __shared__ float sh[6][2];
    if (lane == 0) { sh[w][0] = s; sh[w][1] = ss; }
    __syncthreads();
    float S = 0.f, SS = 0.f;
#pragma unroll
    for (int q = 0; q < 6; q++) { S += sh[q][0]; SS += sh[q][1]; }
    float m = S * (1.f / 768.f);
    float r = rsqrtf(SS * (1.f / 768.f) - m * m + EPS);
    float4 gv = *(const float4*)(g + c);
    float4 bv = *(const float4*)(b + c);
    float4 o;
    o.x = (xv.x - m) * r * gv.x + bv.x;
    o.y = (xv.y - m) * r * gv.y + bv.y;
    o.z = (xv.z - m) * r * gv.z + bv.z;
    o.w = (xv.w - m) * r * gv.w + bv.w;
    *(float4*)(g_xn + i * 768 + c) = o;
}

// ---------------- qkv split: QK-LN + head reshapes ----------------
__global__ void __launch_bounds__(192) qkv_prep_kernel(const float* __restrict__ qg,
                                                       const float* __restrict__ qb,
                                                       const float* __restrict__ kg,
                                                       const float* __restrict__ kb) {
    int i = blockIdx.x, p = blockIdx.y, t = threadIdx.x;
    int c = t * 4;
    const float* row = g_qkv + i * 2304 + p * 768;
    float4 xv = *(const float4*)(row + c);
    int h = c >> 6, d = c & 63;
    if (p == 2) {
        *(float4*)(g_vh + (h * 512 + i) * 64 + d) = xv;
        return;
    }
    float s = xv.x + xv.y + xv.z + xv.w;
    float ss = xv.x * xv.x + xv.y * xv.y + xv.z * xv.z + xv.w * xv.w;
    int lane = t & 31, w = t >> 5;
#pragma unroll
    for (int o = 16; o; o >>= 1) {
        s += __shfl_xor_sync(0xffffffffu, s, o);
        ss += __shfl_xor_sync(0xffffffffu, ss, o);
    }
    __shared__ float sh[6][2];
    if (lane == 0) { sh[w][0] = s; sh[w][1] = ss; }
    __syncthreads();
    float S = 0.f, SS = 0.f;
#pragma unroll
    for (int q = 0; q < 6; q++) { S += sh[q][0]; SS += sh[q][1]; }
    float m = S * (1.f / 768.f);
    float r = rsqrtf(SS * (1.f / 768.f) - m * m + EPS);
    const float* gg = (p == 0) ? qg : kg;
    const float* bb = (p == 0) ? qb : kb;
    float4 gv = *(const float4*)(gg + c);
    float4 bv = *(const float4*)(bb + c);
    float v0 = (xv.x - m) * r * gv.x + bv.x;
    float v1 = (xv.y - m) * r * gv.y + bv.y;
    float v2 = (xv.z - m) * r * gv.z + bv.z;
    float v3 = (xv.w - m) * r * gv.w + bv.w;
    if (p == 0) {
        float4 o = make_float4(v0 * 0.125f, v1 * 0.125f, v2 * 0.125f, v3 * 0.125f);
        *(float4*)(g_qh + (h * 512 + i) * 64 + d) = o;
    } else {
        float* kp = g_kT + h * (64 * 512) + d * 512 + i;
        kp[0] = v0; kp[512] = v1; kp[1024] = v2; kp[1536] = v3;
    }
}

// ---------------- pair-bias v9: 16-ch chunks, swizzled stride-16, 3 blk/SM -
// grid (2,512), 256 thr = 8 warps. Warp w owns rows jw..jw+31, lane owns one
// row (no reductions). Chunk = 16 channels x 32 rows (2KB/warp), 2 buffers,
// 1 chunk always in flight. Staging stride 16 floats with seg swizzle
// phys = (seg + (row>>1)) & 3 -> conflict-free STS and LDS.128 phases.
// cp.async.cg bypasses L1 (streaming). Weights: 36KB smem, warp-uniform
// LDS.128 of pre-packed f32x2 pairs. smem 68KB -> 3 blocks/SM (24 warps).
__global__ void __launch_bounds__(256) pair_bias_kernel(const float* __restrict__ pair) {
    int jt = blockIdx.x, i = blockIdx.y;
    if (jt * 256 > i) return;                  // block-uniform dead exit
    extern __shared__ __align__(16) ull dsm[];
    ull* sgW = dsm;                            // 4608 ull = 36 KB
    float* stg = (float*)(dsm + 4608);         // 8 warps x 2 bufs x 512 floats
    {
        const ull* src = (const ull*)g_gW;
        for (int idx = threadIdx.x; idx < 4608; idx += 256)
            sgW[idx] = src[idx];
    }
    __syncthreads();

    int w = threadIdx.x >> 5, lane = threadIdx.x & 31;
    int jw = jt * 256 + w * 32;
    if (jw > i) return;                        // dead warp (after the sync)
    int j = jw + lane;
    bool live = (j <= i);

    // loader task f = p*32+lane -> row f>>2 (= p*8 + (lane>>2)), seg f&3
    const float* gsrc = pair + ((size_t)i * 512 + jw + (lane >> 2)) * 768 + (lane & 3) * 4;
    float* bufq = stg + w * 1024;              // 2 bufs x 512 floats
    int wrPhys = ((lane & 3) + (lane >> 3)) & 3;   // (seg + (row>>1))&3, p-invariant
    unsigned int sdst = (unsigned int)__cvta_generic_to_shared(
        bufq + (lane >> 2) * 16 + wrPhys * 4);
    const unsigned int BUFB = 512 * 4;         // bytes per buffer
    const unsigned int PSTP = 8 * 16 * 4;      // bytes per p-step (8 rows)

    ull S[6] = {0,0,0,0,0,0};
    ull sss = 0ull;                            // packed (s, ss)

    // prologue: chunks 0 (buf0) and 1 (buf1)
#pragma unroll
    for (int c = 0; c < 2; c++) {
#pragma unroll
        for (int p = 0; p < 4; p++)
            CP_ASYNC16CG(sdst + c * BUFB + p * PSTP, gsrc + c * 16 + (size_t)p * 8 * 768);
        CP_COMMIT();
    }

    int rdSh = lane >> 1;                      // (row>>1) with row = lane
    for (int cc = 0; cc < 48; cc++) {
        if (cc < 47) { CP_WAIT1(); } else { CP_WAIT0(); }
        __syncwarp();                          // chunk cc visible to all lanes
        const float* xr = bufq + (cc & 1) * 512 + lane * 16;
#pragma unroll
        for (int q = 0; q < 4; q++) {
            float4 xv = *(const float4*)(xr + ((q + rdSh) & 3) * 4);
            float xs[4] = {xv.x, xv.y, xv.z, xv.w};
#pragma unroll
            for (int k = 0; k < 4; k++) {
                int ch = cc * 16 + q * 4 + k;
                const ulonglong2* wp = (const ulonglong2*)&sgW[ch * 6];
                ulonglong2 q0 = wp[0];
                ulonglong2 q1 = wp[1];
                ulonglong2 q2 = wp[2];
                float x = xs[k];
                ull xx = pk2(x, x);
                sss = fma2(xx, pk2(1.0f, x), sss);
                S[0] = fma2(xx, q0.x, S[0]);
                S[1] = fma2(xx, q0.y, S[1]);
                S[2] = fma2(xx, q1.x, S[2]);
                S[3] = fma2(xx, q1.y, S[3]);
                S[4] = fma2(xx, q2.x, S[4]);
                S[5] = fma2(xx, q2.y, S[5]);
            }
        }
        __syncwarp();                          // compute done before buf reuse
        if (cc + 2 < 48) {                     // refill the buffer just freed
#pragma unroll
            for (int p = 0; p < 4; p++)
                CP_ASYNC16CG(sdst + (cc & 1) * BUFB + p * PSTP,
                             gsrc + (cc + 2) * 16 + (size_t)p * 8 * 768);
            CP_COMMIT();
        }
    }

    if (!live) return;
    float s, ss; unpk2(s, ss, sss);
    float m = s * (1.f / 768.f);
    float r = rsqrtf(ss * (1.f / 768.f) - m * m + EPS);
    size_t pos = (size_t)i * 512 + j;
#pragma unroll
    for (int h2 = 0; h2 < 6; h2++) {
        float lo, hi; unpk2(lo, hi, S[h2]);
        g_bias[(size_t)(2 * h2) * (512 * 512) + pos] =
            r * (lo - m * __ldg(&g_GW[2 * h2])) + __ldg(&g_BW[2 * h2]);
        g_bias[(size_t)(2 * h2 + 1) * (512 * 512) + pos] =
            r * (hi - m * __ldg(&g_GW[2 * h2 + 1])) + __ldg(&g_BW[2 * h2 + 1]);
    }
}

// ---------------- f32x2 GEMM (R6 known-good): N-packed acc, double-buffered
template <int BM, int BN, int TM, int TN>
__device__ __forceinline__ void gemm2_body(const float* __restrict__ A,
                                           const float* __restrict__ B,
                                           float* __restrict__ C,
                                           const float* __restrict__ biasRow,
                                           const float* __restrict__ biasMat,
                                           int K, int lda, int ldb, int ldc) {
    constexpr int THREADS = (BM / TM) * (BN / TN);
    static_assert(THREADS == 256 && TM == 4, "shape");
    __shared__ __align__(16) float As[2][8][BM];
    __shared__ __align__(16) float Bs[2][8][BN];

    int tid = threadIdx.x;
    int tx = tid % (BN / TN), ty = tid / (BN / TN);
    int m0 = blockIdx.y * BM, n0 = blockIdx.x * BN;

    ull acc[TM][TN / 2];
#pragma unroll
    for (int ii = 0; ii < TM; ii++)
#pragma unroll
        for (int j2 = 0; j2 < TN / 2; j2++) acc[ii][j2] = 0ull;

    bool aact = tid < 2 * BM;
    bool bact = tid < 2 * BN;
    int ar = tid >> 1, ac = (tid & 1) * 4;
    int br = tid / (BN / 4), bc = (tid % (BN / 4)) * 4;

    float4 pa = make_float4(0.f, 0.f, 0.f, 0.f), pb = pa;
    if (aact) pa = *(const float4*)(A + (size_t)(m0 + ar) * lda + ac);
    if (bact) pb = *(const float4*)(B + (size_t)br * ldb + n0 + bc);
    if (aact) {
        As[0][ac + 0][ar] = pa.x; As[0][ac + 1][ar] = pa.y;
        As[0][ac + 2][ar] = pa.z; As[0][ac + 3][ar] = pa.w;
    }
    if (bact) *(float4*)&Bs[0][br][bc] = pb;
    __syncthreads();

    int sb = 0;
    for (int k0 = 0; k0 < K; k0 += 8) {
        bool more = (k0 + 8 < K);
        if (more) {
            if (aact) pa = *(const float4*)(A + (size_t)(m0 + ar) * lda + k0 + 8 + ac);
            if (bact) pb = *(const float4*)(B + (size_t)(k0 + 8 + br) * ldb + n0 + bc);
        }
#pragma unroll
        for (int kk = 0; kk < 8; kk++) {
            float4 av = *(const float4*)&As[sb][kk][ty * TM];
            float a4[4] = {av.x, av.y, av.z, av.w};
            ull b2[TN / 2];
            const ull* bp = (const ull*)&Bs[sb][kk][tx * TN];
#pragma unroll
            for (int j2 = 0; j2 < TN / 2; j2++) b2[j2] = bp[j2];
#pragma unroll
            for (int ii = 0; ii < TM; ii++) {
                ull aa = pk2(a4[ii], a4[ii]);
#pragma unroll
                for (int j2 = 0; j2 < TN / 2; j2++)
                    acc[ii][j2] = fma2(aa, b2[j2], acc[ii][j2]);
            }
        }
        if (more) {
            if (aact) {
                As[sb ^ 1][ac + 0][ar] = pa.x; As[sb ^ 1][ac + 1][ar] = pa.y;
                As[sb ^ 1][ac + 2][ar] = pa.z; As[sb ^ 1][ac + 3][ar] = pa.w;
            }
            if (bact) *(float4*)&Bs[sb ^ 1][br][bc] = pb;
            __syncthreads();
            sb ^= 1;
        }
    }

    float bv[TN];
#pragma unroll
    for (int c = 0; c < TN; c++)
        bv[c] = biasRow ? biasRow[n0 + tx * TN + c] : 0.f;

#pragma unroll
    for (int ii = 0; ii < TM; ii++) {
        int r = m0 + ty * TM + ii;
        float o[TN];
#pragma unroll
        for (int j2 = 0; j2 < TN / 2; j2++) {
            unpk2(o[2 * j2], o[2 * j2 + 1], acc[ii][j2]);
            o[2 * j2] += bv[2 * j2];
            o[2 * j2 + 1] += bv[2 * j2 + 1];
        }
        if (biasMat) {
            const float* bm = biasMat + (size_t)r * ldc + n0 + tx * TN;
#pragma unroll
            for (int c4 = 0; c4 < TN / 4; c4++) {
                float4 mv = *(const float4*)(bm + 4 * c4);
                o[4*c4+0] += mv.x; o[4*c4+1] += mv.y;
                o[4*c4+2] += mv.z; o[4*c4+3] += mv.w;
            }
        }
        float* cp = C + (size_t)r * ldc + n0 + tx * TN;
#pragma unroll
        for (int c4 = 0; c4 < TN / 4; c4++)
            *(float4*)(cp + 4 * c4) = make_float4(o[4*c4], o[4*c4+1], o[4*c4+2], o[4*c4+3]);
    }
}

__global__ void __launch_bounds__(256) gemm_qkv(const float* __restrict__ W,
                                                const float* __restrict__ bias) {
    gemm2_body<64, 64, 4, 4>(g_xn, W, g_qkv, bias, nullptr, 768, 768, 2304, 2304);
}
__global__ void __launch_bounds__(256) gemm_qk() {
    int h = blockIdx.z;
    gemm2_body<64, 128, 4, 8>(g_qh + h * (512 * 64), g_kT + h * (64 * 512),
                              g_sim + (size_t)h * (512 * 512), nullptr,
                              g_bias + (size_t)h * (512 * 512), 64, 64, 512, 512);
}
__global__ void __launch_bounds__(256) gemm_pv() {
    int h = blockIdx.z;
    gemm2_body<64, 64, 4, 4>(g_sim + (size_t)h * (512 * 512), g_vh + h * (512 * 64),
                             g_attout + h * 64, nullptr, nullptr, 512, 512, 64, 768);
}
__global__ void __launch_bounds__(256) gemm_proj(const float* __restrict__ W,
                                                 const float* __restrict__ bias,
                                                 float* __restrict__ out) {
    gemm2_body<64, 64, 4, 4>(g_attout, W, out, bias, nullptr, 768, 768, 768, 768);
}

// ---------------- softmax: warp per (h,i) row, registers only ----------------
__global__ void __launch_bounds__(256) softmax_kernel() {
    int warp = threadIdx.x >> 5, lane = threadIdx.x & 31;
    int rowid = blockIdx.x * 8 + warp;              // 0..6143
    float* row = g_sim + (size_t)rowid * 512;
    float v[16];
    float4* rp = (float4*)(row + lane * 16);
    float4 r0 = rp[0], r1 = rp[1], r2 = rp[2], r3 = rp[3];
    v[0]=r0.x; v[1]=r0.y; v[2]=r0.z; v[3]=r0.w;
    v[4]=r1.x; v[5]=r1.y; v[6]=r1.z; v[7]=r1.w;
    v[8]=r2.x; v[9]=r2.y; v[10]=r2.z; v[11]=r2.w;
    v[12]=r3.x; v[13]=r3.y; v[14]=r3.z; v[15]=r3.w;
    float m = v[0];
#pragma unroll
    for (int e = 1; e < 16; e++) m = fmaxf(m, v[e]);
#pragma unroll
    for (int o = 16; o; o >>= 1) m = fmaxf(m, __shfl_xor_sync(0xffffffffu, m, o));
    float s = 0.f;
#pragma unroll
    for (int e = 0; e < 16; e++) { v[e] = __expf(v[e] - m); s += v[e]; }
#pragma unroll
    for (int o = 16; o; o >>= 1) s += __shfl_xor_sync(0xffffffffu, s, o);
    float inv = __fdividef(1.f, s);
    rp[0] = make_float4(v[0]*inv, v[1]*inv, v[2]*inv, v[3]*inv);
    rp[1] = make_float4(v[4]*inv, v[5]*inv, v[6]*inv, v[7]*inv);
    rp[2] = make_float4(v[8]*inv, v[9]*inv, v[10]*inv, v[11]*inv);
    rp[3] = make_float4(v[12]*inv, v[13]*inv, v[14]*inv, v[15]*inv);
}

// ---------------- launch ----------------
extern "C" void kernel_launch(void* const* d_in, const int* in_sizes, int n_in,
                              void* d_out, int out_size) {
    int base = n_in - 13;                     // norm_g index (mask-type agnostic)
    const float* x      = (const float*)d_in[0];
    const float* pair   = (const float*)d_in[1];
    const float* norm_g = (const float*)d_in[base + 0];
    const float* norm_b = (const float*)d_in[base + 1];
    const float* Wqkv   = (const float*)d_in[base + 2];
    const float* bqkv   = (const float*)d_in[base + 3];
    const float* qln_g  = (const float*)d_in[base + 4];
    const float* qln_b  = (const float*)d_in[base + 5];
    const float* kln_g  = (const float*)d_in[base + 6];
    const float* kln_b  = (const float*)d_in[base + 7];
    const float* pair_g = (const float*)d_in[base + 8];
    const float* pair_b = (const float*)d_in[base + 9];
    const float* Wbias  = (const float*)d_in[base + 10];
    const float* Wproj  = (const float*)d_in[base + 11];
    const float* bproj  = (const float*)d_in[base + 12];
    float* out = (float*)d_out;

    const int PB_SMEM = 4608 * 8 + 8 * 2 * 512 * 4;   // 36KB weights + 32KB staging
    cudaFuncSetAttribute(pair_bias_kernel,
                         cudaFuncAttributeMaxDynamicSharedMemorySize, PB_SMEM);

    precompute_gw<<<1, 384>>>(pair_g, pair_b, Wbias);              // 1
    ln_x_kernel<<<512, 192>>>(x, norm_g, norm_b);                  // 2
    gemm_qkv<<<dim3(36, 8), 256>>>(Wqkv, bqkv);                    // 3
    pair_bias_kernel<<<dim3(2, 512), 256, PB_SMEM>>>(pair);        // 4 <- profiled
    qkv_prep_kernel<<<dim3(512, 3), 192>>>(qln_g, qln_b, kln_g, kln_b); // 5
    gemm_qk<<<dim3(4, 8, 12), 256>>>();                            // 6
    softmax_kernel<<<768, 256>>>();                                // 7
    gemm_pv<<<dim3(1, 8, 12), 256>>>();                            // 8
    gemm_proj<<<dim3(12, 8), 256>>>(Wproj, bproj, out);            // 9
}